// round 5
// baseline (speedup 1.0000x reference)
#include <cuda_runtime.h>

#define TPB 416        // 32 batch elems * 13 nodes
#define NB  32         // batch elems per block
#define NGRID 1024     // 32768 / 32

#define ARENA_BYTES 6048
#define SMEM_TOTAL  (NB * ARENA_BYTES)   // 193536

// ---- packed weights in global memory (prepared by prep_kernel) ----
// float4 units
#define OFF_W0    0
#define OFF_W1    256
#define OFF_DEC   512
#define OFF_FC1   768
#define OFF_FC2   832
#define OFF_B0    896
#define OFF_B1    912
#define OFF_DECB  928
#define OFF_FC1B  944
#define OFF_FC2B  948
#define OFF_WINIT 952   // 52 entries -> end 1004

__device__ float4 g_w4[1008];
__device__ float2 g_bnin[52];
__device__ float2 g_bnout[52];
__device__ float  g_eps[4];

// packed f32x2 FMA (sm_100+): r = a*b + c per 32-bit half
__device__ __forceinline__ float2 ffma2(float2 a, float2 b, float2 c) {
    unsigned long long ua = *reinterpret_cast<unsigned long long*>(&a);
    unsigned long long ub = *reinterpret_cast<unsigned long long*>(&b);
    unsigned long long uc = *reinterpret_cast<unsigned long long*>(&c);
    unsigned long long ur;
    asm("fma.rn.f32x2 %0, %1, %2, %3;" : "=l"(ur) : "l"(ua), "l"(ub), "l"(uc));
    return *reinterpret_cast<float2*>(&ur);
}

__device__ __forceinline__ float2 lo2(float4 v) { return make_float2(v.x, v.y); }
__device__ __forceinline__ float2 hi2(float4 v) { return make_float2(v.z, v.w); }

__device__ __forceinline__ float getf2(const float2* v, int d) {
    return (d & 1) ? v[d >> 1].y : v[d >> 1].x;
}

__device__ __forceinline__ float lky(float v) { return fmaxf(v, 0.01f * v); }

// 16x16 matmul: out2[8] (pairs over d') += sum_d in(d) * Wq[d][4 float4]
// Wq in GLOBAL memory, uniform address across warp -> 1-line LDG per load
__device__ __forceinline__ void mm16(float2* out2, const float2* in2, const float4* Wq) {
#pragma unroll
    for (int d = 0; d < 16; d++) {
        float a = getf2(in2, d);
        float2 ap = make_float2(a, a);
        float4 q0 = __ldg(Wq + d * 4 + 0);
        float4 q1 = __ldg(Wq + d * 4 + 1);
        float4 q2 = __ldg(Wq + d * 4 + 2);
        float4 q3 = __ldg(Wq + d * 4 + 3);
        out2[0] = ffma2(ap, lo2(q0), out2[0]);
        out2[1] = ffma2(ap, hi2(q0), out2[1]);
        out2[2] = ffma2(ap, lo2(q1), out2[2]);
        out2[3] = ffma2(ap, hi2(q1), out2[3]);
        out2[4] = ffma2(ap, lo2(q2), out2[4]);
        out2[5] = ffma2(ap, hi2(q2), out2[5]);
        out2[6] = ffma2(ap, lo2(q3), out2[6]);
        out2[7] = ffma2(ap, hi2(q3), out2[7]);
    }
}

__device__ __forceinline__ void load8(float2* dst, const float4* src) {
    float4 c0 = __ldg(src + 0), c1 = __ldg(src + 1), c2 = __ldg(src + 2), c3 = __ldg(src + 3);
    dst[0] = lo2(c0); dst[1] = hi2(c0); dst[2] = lo2(c1); dst[3] = hi2(c1);
    dst[4] = lo2(c2); dst[5] = hi2(c2); dst[6] = lo2(c3); dst[7] = hi2(c3);
}

// ---- prep kernel: pack/transpose weights + fold BN into global tables ----
__global__ void prep_kernel(
    const float* __restrict__ init_weight, const float* __restrict__ eps_param,
    const float* __restrict__ mlp_w0, const float* __restrict__ mlp_b0,
    const float* __restrict__ mlp_w1, const float* __restrict__ mlp_b1,
    const float* __restrict__ bn_in_gamma, const float* __restrict__ bn_in_beta,
    const float* __restrict__ bn_in_mean,  const float* __restrict__ bn_in_var,
    const float* __restrict__ bn_out_gamma, const float* __restrict__ bn_out_beta,
    const float* __restrict__ bn_out_mean,  const float* __restrict__ bn_out_var,
    const float* __restrict__ fc1_w, const float* __restrict__ fc1_b,
    const float* __restrict__ fc2_w, const float* __restrict__ fc2_b,
    const float* __restrict__ dec_w, const float* __restrict__ dec_b)
{
    int t = threadIdx.x;   // 256 threads
    if (t < 256) {
        int l = t >> 6, d = (t >> 2) & 15, q = t & 3;
        const float* w  = mlp_w0 + l * 256;
        const float* w1 = mlp_w1 + l * 256;
        const float* dw = dec_w  + l * 256;
        g_w4[OFF_W0 + t]  = make_float4(w [(4*q+0)*16+d], w [(4*q+1)*16+d], w [(4*q+2)*16+d], w [(4*q+3)*16+d]);
        g_w4[OFF_W1 + t]  = make_float4(w1[(4*q+0)*16+d], w1[(4*q+1)*16+d], w1[(4*q+2)*16+d], w1[(4*q+3)*16+d]);
        g_w4[OFF_DEC + t] = make_float4(dw[(4*q+0)*16+d], dw[(4*q+1)*16+d], dw[(4*q+2)*16+d], dw[(4*q+3)*16+d]);
    }
    if (t < 64) {
        int d = t >> 2, q = t & 3;
        g_w4[OFF_FC1 + t] = make_float4(fc1_w[(4*q+0)*16+d], fc1_w[(4*q+1)*16+d], fc1_w[(4*q+2)*16+d], fc1_w[(4*q+3)*16+d]);
        g_w4[OFF_FC2 + t] = make_float4(fc2_w[(4*q+0)*16+d], fc2_w[(4*q+1)*16+d], fc2_w[(4*q+2)*16+d], fc2_w[(4*q+3)*16+d]);
    }
    if (t < 52) g_w4[OFF_WINIT + t] = ((const float4*)init_weight)[t];
    if (t < 16) {
        g_w4[OFF_B0 + t]   = ((const float4*)mlp_b0)[t];
        g_w4[OFF_B1 + t]   = ((const float4*)mlp_b1)[t];
        g_w4[OFF_DECB + t] = ((const float4*)dec_b)[t];
    }
    if (t < 4) {
        g_w4[OFF_FC1B + t] = ((const float4*)fc1_b)[t];
        g_w4[OFF_FC2B + t] = ((const float4*)fc2_b)[t];
        g_eps[t] = 1.0f + eps_param[t];
    }
    if (t < 52) {
        float s = bn_in_gamma[t] * rsqrtf(bn_in_var[t] + 1e-5f);
        g_bnin[t] = make_float2(s, bn_in_beta[t] - bn_in_mean[t] * s);
        float so = bn_out_gamma[t] * rsqrtf(bn_out_var[t] + 1e-5f);
        g_bnout[t] = make_float2(so, bn_out_beta[t] - bn_out_mean[t] * so);
    }
}

__global__ __launch_bounds__(TPB, 1)
void vae_kernel(const float* __restrict__ adj, float* __restrict__ d_out)
{
    extern __shared__ char sm[];
    char* arenas = sm;

    const int t = threadIdx.x;

    // ---- load adj (coalesced float4) into per-b arenas ----
    const float4* adjg = (const float4*)(adj + (size_t)blockIdx.x * NB * 676);
    for (int i = t; i < NB * 169; i += TPB) {           // 13 iters exactly
        int b = i / 169, q = i - b * 169;
        *(float4*)(arenas + b * ARENA_BYTES + q * 16) = adjg[i];
    }
    __syncthreads();

    // ---- per-thread: (bl, n) ----
    const int bl = t / 13;
    const int n  = t - bl * 13;
    char*   arena = arenas + bl * ARENA_BYTES;
    float*  adjS  = (float*)arena;                 // [g*169 + n*13 + m]
    float4* xb0   = (float4*)(arena + 2704);       // [13][4]
    float4* xb1   = (float4*)(arena + 3536);       // [13][4]

    // x init: asum over channels, then @ init_weight
    float asum[13];
#pragma unroll
    for (int m = 0; m < 13; m++) {
        int o = n * 13 + m;
        asum[m] = adjS[o] + adjS[169 + o] + adjS[338 + o] + adjS[507 + o];
    }
    float2 x2[8];
#pragma unroll
    for (int j = 0; j < 8; j++) x2[j] = make_float2(0.f, 0.f);
#pragma unroll
    for (int m = 0; m < 13; m++) {
        float2 ap = make_float2(asum[m], asum[m]);
        float4 q0 = __ldg(&g_w4[OFF_WINIT + m*4+0]);
        float4 q1 = __ldg(&g_w4[OFF_WINIT + m*4+1]);
        float4 q2 = __ldg(&g_w4[OFF_WINIT + m*4+2]);
        float4 q3 = __ldg(&g_w4[OFF_WINIT + m*4+3]);
        x2[0] = ffma2(ap, lo2(q0), x2[0]);  x2[1] = ffma2(ap, hi2(q0), x2[1]);
        x2[2] = ffma2(ap, lo2(q1), x2[2]);  x2[3] = ffma2(ap, hi2(q1), x2[3]);
        x2[4] = ffma2(ap, lo2(q2), x2[4]);  x2[5] = ffma2(ap, hi2(q2), x2[5]);
        x2[6] = ffma2(ap, lo2(q3), x2[6]);  x2[7] = ffma2(ap, hi2(q3), x2[7]);
    }
#pragma unroll
    for (int q = 0; q < 4; q++)
        xb0[n*4+q] = make_float4(x2[2*q].x, x2[2*q].y, x2[2*q+1].x, x2[2*q+1].y);
    __syncthreads();

    // ---- 4 GIN layers (double-buffered x rows: one sync per layer) ----
#pragma unroll
    for (int l = 0; l < 4; l++) {
        const float4* xrd = (l & 1) ? xb1 : xb0;
        float4*       xwr = (l & 1) ? xb0 : xb1;

        // neighbor: group g = d/4 uses adj channel g
        float2 nb2[8];
#pragma unroll
        for (int j = 0; j < 8; j++) nb2[j] = make_float2(0.f, 0.f);
#pragma unroll
        for (int m = 0; m < 13; m++) {
            int o = n * 13 + m;
            float a0 = adjS[o], a1 = adjS[169 + o], a2v = adjS[338 + o], a3 = adjS[507 + o];
            float2 g0 = make_float2(a0, a0), g1 = make_float2(a1, a1);
            float2 g2 = make_float2(a2v, a2v), g3 = make_float2(a3, a3);
            float4 m0 = xrd[m*4+0], m1 = xrd[m*4+1], m2 = xrd[m*4+2], m3 = xrd[m*4+3];
            nb2[0] = ffma2(g0, lo2(m0), nb2[0]);  nb2[1] = ffma2(g0, hi2(m0), nb2[1]);
            nb2[2] = ffma2(g1, lo2(m1), nb2[2]);  nb2[3] = ffma2(g1, hi2(m1), nb2[3]);
            nb2[4] = ffma2(g2, lo2(m2), nb2[4]);  nb2[5] = ffma2(g2, hi2(m2), nb2[5]);
            nb2[6] = ffma2(g3, lo2(m3), nb2[6]);  nb2[7] = ffma2(g3, hi2(m3), nb2[7]);
        }
        float e = __ldg(&g_eps[l]);
        float2 ep = make_float2(e, e);
        float2 agg2[8];
#pragma unroll
        for (int j = 0; j < 8; j++) agg2[j] = ffma2(ep, x2[j], nb2[j]);

        // h1 = agg @ w0^T + b0 -> BN_in -> leaky
        float2 h2[8];
        load8(h2, &g_w4[OFF_B0 + l*4]);
        mm16(h2, agg2, &g_w4[OFF_W0 + l * 64]);
        {
            float2 st = __ldg(&g_bnin[l * 13 + n]);
            float2 sp = make_float2(st.x, st.x), tp = make_float2(st.y, st.y);
#pragma unroll
            for (int j = 0; j < 8; j++) {
                h2[j] = ffma2(sp, h2[j], tp);
                h2[j].x = lky(h2[j].x); h2[j].y = lky(h2[j].y);
            }
        }
        // out = h1 @ w1^T + b1 -> BN_out -> leaky -> new x
        float2 o2[8];
        load8(o2, &g_w4[OFF_B1 + l*4]);
        mm16(o2, h2, &g_w4[OFF_W1 + l * 64]);
        {
            float2 st = __ldg(&g_bnout[l * 13 + n]);
            float2 sp = make_float2(st.x, st.x), tp = make_float2(st.y, st.y);
#pragma unroll
            for (int j = 0; j < 8; j++) {
                o2[j] = ffma2(sp, o2[j], tp);
                o2[j].x = lky(o2[j].x); o2[j].y = lky(o2[j].y);
                x2[j] = o2[j];
            }
        }
        if (l < 3) {
#pragma unroll
            for (int q = 0; q < 4; q++)
                xwr[n*4+q] = make_float4(x2[2*q].x, x2[2*q].y, x2[2*q+1].x, x2[2*q+1].y);
            __syncthreads();
        }
    }

    // ---- fc heads: mu, logvar ----
    float2 mu2[8], lv2[8];
    load8(mu2, &g_w4[OFF_FC1B]);
    load8(lv2, &g_w4[OFF_FC2B]);
    mm16(mu2, x2, &g_w4[OFF_FC1]);
    mm16(lv2, x2, &g_w4[OFF_FC2]);
    {
        size_t bg = (size_t)blockIdx.x * NB + bl;
        float* muo = d_out + 22151168ull + (bg * 13 + n) * 16;
        float* lvo = d_out + 28966912ull + (bg * 13 + n) * 16;
#pragma unroll
        for (int q = 0; q < 4; q++) {
            ((float4*)muo)[q] = make_float4(mu2[2*q].x, mu2[2*q].y, mu2[2*q+1].x, mu2[2*q+1].y);
            ((float4*)lvo)[q] = make_float4(lv2[2*q].x, lv2[2*q].y, lv2[2*q+1].x, lv2[2*q+1].y);
        }
    }

    // Fence: layer-3 adj reads + xb1 reads must complete before tS overlay
    __syncthreads();

    // ---- decoder: temp[k][n][d] = mu @ dec_w[k]^T + dec_b[k] ----
    float4* tS = (float4*)arena;   // [k*52 + m*4 + q], overlays adj + xb0
#pragma unroll
    for (int k = 0; k < 4; k++) {
        float2 acc[8];
        load8(acc, &g_w4[OFF_DECB + k*4]);
        mm16(acc, mu2, &g_w4[OFF_DEC + k * 64]);
#pragma unroll
        for (int q = 0; q < 4; q++)
            tS[k*52 + n*4 + q] = make_float4(acc[2*q].x, acc[2*q].y, acc[2*q+1].x, acc[2*q+1].y);
    }
    __syncthreads();

    // ---- recon[k][n][m] = relu(<t[k][n], t[k][m]>), SYMMETRIC: compute m<=n, mirror ----
    float* reconS = (float*)(arena + 3328);  // [k*169 + n*13 + m]
#pragma unroll
    for (int k = 0; k < 4; k++) {
        float2 tn[8];
        {
            float4 q0 = tS[k*52+n*4+0], q1 = tS[k*52+n*4+1], q2 = tS[k*52+n*4+2], q3 = tS[k*52+n*4+3];
            tn[0] = lo2(q0); tn[1] = hi2(q0); tn[2] = lo2(q1); tn[3] = hi2(q1);
            tn[4] = lo2(q2); tn[5] = hi2(q2); tn[6] = lo2(q3); tn[7] = hi2(q3);
        }
        for (int m = 0; m <= n; m++) {
            float4 q0 = tS[k*52+m*4+0], q1 = tS[k*52+m*4+1], q2 = tS[k*52+m*4+2], q3 = tS[k*52+m*4+3];
            float2 acc = make_float2(0.f, 0.f);
            acc = ffma2(tn[0], lo2(q0), acc);  acc = ffma2(tn[1], hi2(q0), acc);
            acc = ffma2(tn[2], lo2(q1), acc);  acc = ffma2(tn[3], hi2(q1), acc);
            acc = ffma2(tn[4], lo2(q2), acc);  acc = ffma2(tn[5], hi2(q2), acc);
            acc = ffma2(tn[6], lo2(q3), acc);  acc = ffma2(tn[7], hi2(q3), acc);
            float v = fmaxf(acc.x + acc.y, 0.0f);
            reconS[k * 169 + n * 13 + m] = v;
            if (m < n) reconS[k * 169 + m * 13 + n] = v;
        }
    }
    __syncthreads();

    // ---- coalesced recon flush (float4) ----
    {
        float4* outg = (float4*)d_out;
        size_t base4 = (size_t)blockIdx.x * NB * 169;
        for (int i = t; i < NB * 169; i += TPB) {       // 13 iters exactly
            int b = i / 169, q = i - b * 169;
            outg[base4 + i] = *(const float4*)(arenas + b * ARENA_BYTES + 3328 + q * 16);
        }
    }
}

extern "C" void kernel_launch(void* const* d_in, const int* in_sizes, int n_in,
                              void* d_out, int out_size) {
    (void)in_sizes; (void)n_in; (void)out_size;
    prep_kernel<<<1, 256>>>(
        (const float*)d_in[1],  (const float*)d_in[2],
        (const float*)d_in[3],  (const float*)d_in[4],  (const float*)d_in[5],
        (const float*)d_in[6],  (const float*)d_in[7],  (const float*)d_in[8],
        (const float*)d_in[9],  (const float*)d_in[10], (const float*)d_in[11],
        (const float*)d_in[12], (const float*)d_in[13], (const float*)d_in[14],
        (const float*)d_in[15], (const float*)d_in[16], (const float*)d_in[17],
        (const float*)d_in[18], (const float*)d_in[19], (const float*)d_in[20]);
    cudaFuncSetAttribute(vae_kernel, cudaFuncAttributeMaxDynamicSharedMemorySize, SMEM_TOTAL);
    vae_kernel<<<NGRID, TPB, SMEM_TOTAL>>>((const float*)d_in[0], (float*)d_out);
}

// round 6
// speedup vs baseline: 1.4100x; 1.4100x over previous
#include <cuda_runtime.h>

#define TPB 208        // 16 bl-groups * 13 nodes; each thread does 2 batch elems
#define NB  32         // batch elems per block
#define NGRID 1024     // 32768 / 32

#define ARENA_BYTES 6048
#define WREG_BYTES  16912
#define SMEM_TOTAL  (WREG_BYTES + NB * ARENA_BYTES)   // 210448

// packed f32x2 FMA (sm_100+): r = a*b + c per 32-bit half
__device__ __forceinline__ float2 ffma2(float2 a, float2 b, float2 c) {
    unsigned long long ua = *reinterpret_cast<unsigned long long*>(&a);
    unsigned long long ub = *reinterpret_cast<unsigned long long*>(&b);
    unsigned long long uc = *reinterpret_cast<unsigned long long*>(&c);
    unsigned long long ur;
    asm("fma.rn.f32x2 %0, %1, %2, %3;" : "=l"(ur) : "l"(ua), "l"(ub), "l"(uc));
    return *reinterpret_cast<float2*>(&ur);
}

__device__ __forceinline__ float2 lo2(float4 v) { return make_float2(v.x, v.y); }
__device__ __forceinline__ float2 hi2(float4 v) { return make_float2(v.z, v.w); }

__device__ __forceinline__ float getf2(const float2* v, int d) {
    return (d & 1) ? v[d >> 1].y : v[d >> 1].x;
}

__device__ __forceinline__ float lky(float v) { return fmaxf(v, 0.01f * v); }

// dual 16x16 matmul: one weight read feeds BOTH accumulator streams
__device__ __forceinline__ void mm16d(float2* oa, float2* ob,
                                      const float2* ia, const float2* ib,
                                      const float4* Wq) {
#pragma unroll
    for (int d = 0; d < 16; d++) {
        float av = getf2(ia, d), bv = getf2(ib, d);
        float2 ap = make_float2(av, av), bp = make_float2(bv, bv);
        float4 q0 = Wq[d * 4 + 0];
        float4 q1 = Wq[d * 4 + 1];
        float4 q2 = Wq[d * 4 + 2];
        float4 q3 = Wq[d * 4 + 3];
        oa[0] = ffma2(ap, lo2(q0), oa[0]);  ob[0] = ffma2(bp, lo2(q0), ob[0]);
        oa[1] = ffma2(ap, hi2(q0), oa[1]);  ob[1] = ffma2(bp, hi2(q0), ob[1]);
        oa[2] = ffma2(ap, lo2(q1), oa[2]);  ob[2] = ffma2(bp, lo2(q1), ob[2]);
        oa[3] = ffma2(ap, hi2(q1), oa[3]);  ob[3] = ffma2(bp, hi2(q1), ob[3]);
        oa[4] = ffma2(ap, lo2(q2), oa[4]);  ob[4] = ffma2(bp, lo2(q2), ob[4]);
        oa[5] = ffma2(ap, hi2(q2), oa[5]);  ob[5] = ffma2(bp, hi2(q2), ob[5]);
        oa[6] = ffma2(ap, lo2(q3), oa[6]);  ob[6] = ffma2(bp, lo2(q3), ob[6]);
        oa[7] = ffma2(ap, hi2(q3), oa[7]);  ob[7] = ffma2(bp, hi2(q3), ob[7]);
    }
}

__device__ __forceinline__ void load8s(float2* dst, const float4* src) {
    float4 c0 = src[0], c1 = src[1], c2 = src[2], c3 = src[3];
    dst[0] = lo2(c0); dst[1] = hi2(c0); dst[2] = lo2(c1); dst[3] = hi2(c1);
    dst[4] = lo2(c2); dst[5] = hi2(c2); dst[6] = lo2(c3); dst[7] = hi2(c3);
}

__global__ __launch_bounds__(TPB, 1)
void vae_kernel(
    const float* __restrict__ adj,          // (B,4,13,13)
    const float* __restrict__ init_weight,  // (13,16)
    const float* __restrict__ eps_param,    // (4)
    const float* __restrict__ mlp_w0,       // (4,16,16)
    const float* __restrict__ mlp_b0,       // (4,16)
    const float* __restrict__ mlp_w1,       // (4,16,16)
    const float* __restrict__ mlp_b1,       // (4,16)
    const float* __restrict__ bn_in_gamma,  // (4,13)
    const float* __restrict__ bn_in_beta,
    const float* __restrict__ bn_in_mean,
    const float* __restrict__ bn_in_var,
    const float* __restrict__ bn_out_gamma,
    const float* __restrict__ bn_out_beta,
    const float* __restrict__ bn_out_mean,
    const float* __restrict__ bn_out_var,
    const float* __restrict__ fc1_w,        // (16,16)
    const float* __restrict__ fc1_b,        // (16)
    const float* __restrict__ fc2_w,
    const float* __restrict__ fc2_b,
    const float* __restrict__ dec_w,        // (4,16,16)
    const float* __restrict__ dec_b,        // (4,16)
    float* __restrict__ d_out)
{
    extern __shared__ char sm[];
    float4* w0q   = (float4*)(sm + 0);      // [4][16][4]
    float4* w1q   = (float4*)(sm + 4096);   // [4][16][4]
    float4* decq  = (float4*)(sm + 8192);   // [4][16][4]
    float4* fc1q  = (float4*)(sm + 12288);  // [16][4]
    float4* fc2q  = (float4*)(sm + 13312);  // [16][4]
    float4* b0q   = (float4*)(sm + 14336);  // [4][4]
    float4* b1q   = (float4*)(sm + 14592);  // [4][4]
    float4* decbq = (float4*)(sm + 14848);  // [4][4]
    float4* fc1bq = (float4*)(sm + 15104);  // [4]
    float4* fc2bq = (float4*)(sm + 15168);  // [4]
    float2* bninq = (float2*)(sm + 15232);  // [4][13] (s,t)
    float2* bnoutq= (float2*)(sm + 15648);  // [4][13] (s,t)
    float4* winitq= (float4*)(sm + 16064);  // [13][4]
    float*  eps1  = (float*)(sm + 16896);   // [4]
    char*   arenas = sm + WREG_BYTES;

    const int t = threadIdx.x;

    // ---- stage transposed/packed weights ----
    for (int idx = t; idx < 256; idx += TPB) {          // 4*16*4
        int l = idx >> 6, d = (idx >> 2) & 15, q = idx & 3;
        const float* w  = mlp_w0 + l * 256;
        const float* w1 = mlp_w1 + l * 256;
        const float* dw = dec_w  + l * 256;
        w0q[idx]  = make_float4(w [(4*q+0)*16+d], w [(4*q+1)*16+d], w [(4*q+2)*16+d], w [(4*q+3)*16+d]);
        w1q[idx]  = make_float4(w1[(4*q+0)*16+d], w1[(4*q+1)*16+d], w1[(4*q+2)*16+d], w1[(4*q+3)*16+d]);
        decq[idx] = make_float4(dw[(4*q+0)*16+d], dw[(4*q+1)*16+d], dw[(4*q+2)*16+d], dw[(4*q+3)*16+d]);
    }
    for (int idx = t; idx < 64; idx += TPB) {           // 16*4
        int d = idx >> 2, q = idx & 3;
        fc1q[idx] = make_float4(fc1_w[(4*q+0)*16+d], fc1_w[(4*q+1)*16+d], fc1_w[(4*q+2)*16+d], fc1_w[(4*q+3)*16+d]);
        fc2q[idx] = make_float4(fc2_w[(4*q+0)*16+d], fc2_w[(4*q+1)*16+d], fc2_w[(4*q+2)*16+d], fc2_w[(4*q+3)*16+d]);
    }
    for (int idx = t; idx < 52; idx += TPB)             // 13*4
        winitq[idx] = ((const float4*)init_weight)[idx];
    for (int idx = t; idx < 16; idx += TPB) {           // 4*4
        b0q[idx]   = ((const float4*)mlp_b0)[idx];
        b1q[idx]   = ((const float4*)mlp_b1)[idx];
        decbq[idx] = ((const float4*)dec_b)[idx];
    }
    if (t < 4) {
        fc1bq[t] = ((const float4*)fc1_b)[t];
        fc2bq[t] = ((const float4*)fc2_b)[t];
        eps1[t]  = 1.0f + eps_param[t];
    }
    for (int idx = t; idx < 52; idx += TPB) {           // 4*13 BN fold
        float s = bn_in_gamma[idx] * rsqrtf(bn_in_var[idx] + 1e-5f);
        bninq[idx] = make_float2(s, bn_in_beta[idx] - bn_in_mean[idx] * s);
        float so = bn_out_gamma[idx] * rsqrtf(bn_out_var[idx] + 1e-5f);
        bnoutq[idx] = make_float2(so, bn_out_beta[idx] - bn_out_mean[idx] * so);
    }

    // ---- load adj (coalesced float4) into per-b arenas ----
    const float4* adjg = (const float4*)(adj + (size_t)blockIdx.x * NB * 676);
    for (int i = t; i < NB * 169; i += TPB) {           // 26 iters exactly
        int b = i / 169, q = i - b * 169;
        *(float4*)(arenas + b * ARENA_BYTES + q * 16) = adjg[i];
    }
    __syncthreads();

    // ---- per-thread: (bl, n) handles arenas bl and bl+16 ----
    const int bl = t / 13;
    const int n  = t - bl * 13;
    char* arA = arenas + bl * ARENA_BYTES;
    char* arB = arenas + (bl + 16) * ARENA_BYTES;
    float*  adjA = (float*)arA;                  // [g*169 + n*13 + m]
    float*  adjB = (float*)arB;
    float4* xA0  = (float4*)(arA + 2704);        // [13][4]
    float4* xA1  = (float4*)(arA + 3536);
    float4* xB0  = (float4*)(arB + 2704);
    float4* xB1  = (float4*)(arB + 3536);

    // ---- x init ----
    float2 xa[8], xb[8];
#pragma unroll
    for (int j = 0; j < 8; j++) { xa[j] = make_float2(0.f, 0.f); xb[j] = make_float2(0.f, 0.f); }
#pragma unroll
    for (int m = 0; m < 13; m++) {
        int o = n * 13 + m;
        float sa = adjA[o] + adjA[169 + o] + adjA[338 + o] + adjA[507 + o];
        float sb = adjB[o] + adjB[169 + o] + adjB[338 + o] + adjB[507 + o];
        float2 ap = make_float2(sa, sa), bp = make_float2(sb, sb);
        float4 q0 = winitq[m*4+0], q1 = winitq[m*4+1], q2 = winitq[m*4+2], q3 = winitq[m*4+3];
        xa[0] = ffma2(ap, lo2(q0), xa[0]);  xb[0] = ffma2(bp, lo2(q0), xb[0]);
        xa[1] = ffma2(ap, hi2(q0), xa[1]);  xb[1] = ffma2(bp, hi2(q0), xb[1]);
        xa[2] = ffma2(ap, lo2(q1), xa[2]);  xb[2] = ffma2(bp, lo2(q1), xb[2]);
        xa[3] = ffma2(ap, hi2(q1), xa[3]);  xb[3] = ffma2(bp, hi2(q1), xb[3]);
        xa[4] = ffma2(ap, lo2(q2), xa[4]);  xb[4] = ffma2(bp, lo2(q2), xb[4]);
        xa[5] = ffma2(ap, hi2(q2), xa[5]);  xb[5] = ffma2(bp, hi2(q2), xb[5]);
        xa[6] = ffma2(ap, lo2(q3), xa[6]);  xb[6] = ffma2(bp, lo2(q3), xb[6]);
        xa[7] = ffma2(ap, hi2(q3), xa[7]);  xb[7] = ffma2(bp, hi2(q3), xb[7]);
    }
#pragma unroll
    for (int q = 0; q < 4; q++) {
        xA0[n*4+q] = make_float4(xa[2*q].x, xa[2*q].y, xa[2*q+1].x, xa[2*q+1].y);
        xB0[n*4+q] = make_float4(xb[2*q].x, xb[2*q].y, xb[2*q+1].x, xb[2*q+1].y);
    }
    __syncthreads();

    // ---- 4 GIN layers ----
#pragma unroll
    for (int l = 0; l < 4; l++) {
        const float4* xrdA = (l & 1) ? xA1 : xA0;
        const float4* xrdB = (l & 1) ? xB1 : xB0;
        float4*       xwrA = (l & 1) ? xA0 : xA1;
        float4*       xwrB = (l & 1) ? xB0 : xB1;

        float2 na[8], nb[8];
#pragma unroll
        for (int j = 0; j < 8; j++) { na[j] = make_float2(0.f, 0.f); nb[j] = make_float2(0.f, 0.f); }
#pragma unroll
        for (int m = 0; m < 13; m++) {
            int o = n * 13 + m;
            {
                float a0 = adjA[o], a1 = adjA[169+o], a2 = adjA[338+o], a3 = adjA[507+o];
                float2 g0 = make_float2(a0,a0), g1 = make_float2(a1,a1);
                float2 g2 = make_float2(a2,a2), g3 = make_float2(a3,a3);
                float4 m0 = xrdA[m*4+0], m1 = xrdA[m*4+1], m2 = xrdA[m*4+2], m3 = xrdA[m*4+3];
                na[0] = ffma2(g0, lo2(m0), na[0]);  na[1] = ffma2(g0, hi2(m0), na[1]);
                na[2] = ffma2(g1, lo2(m1), na[2]);  na[3] = ffma2(g1, hi2(m1), na[3]);
                na[4] = ffma2(g2, lo2(m2), na[4]);  na[5] = ffma2(g2, hi2(m2), na[5]);
                na[6] = ffma2(g3, lo2(m3), na[6]);  na[7] = ffma2(g3, hi2(m3), na[7]);
            }
            {
                float a0 = adjB[o], a1 = adjB[169+o], a2 = adjB[338+o], a3 = adjB[507+o];
                float2 g0 = make_float2(a0,a0), g1 = make_float2(a1,a1);
                float2 g2 = make_float2(a2,a2), g3 = make_float2(a3,a3);
                float4 m0 = xrdB[m*4+0], m1 = xrdB[m*4+1], m2 = xrdB[m*4+2], m3 = xrdB[m*4+3];
                nb[0] = ffma2(g0, lo2(m0), nb[0]);  nb[1] = ffma2(g0, hi2(m0), nb[1]);
                nb[2] = ffma2(g1, lo2(m1), nb[2]);  nb[3] = ffma2(g1, hi2(m1), nb[3]);
                nb[4] = ffma2(g2, lo2(m2), nb[4]);  nb[5] = ffma2(g2, hi2(m2), nb[5]);
                nb[6] = ffma2(g3, lo2(m3), nb[6]);  nb[7] = ffma2(g3, hi2(m3), nb[7]);
            }
        }
        float e = eps1[l];
        float2 ep = make_float2(e, e);
        float2 aga[8], agb[8];
#pragma unroll
        for (int j = 0; j < 8; j++) {
            aga[j] = ffma2(ep, xa[j], na[j]);
            agb[j] = ffma2(ep, xb[j], nb[j]);
        }

        // h1 = agg @ w0^T + b0 -> BN_in -> leaky
        float2 ha[8], hb[8];
        load8s(ha, &b0q[l*4]); load8s(hb, &b0q[l*4]);
        mm16d(ha, hb, aga, agb, &w0q[l * 64]);
        {
            float2 st = bninq[l * 13 + n];
            float2 sp = make_float2(st.x, st.x), tp = make_float2(st.y, st.y);
#pragma unroll
            for (int j = 0; j < 8; j++) {
                ha[j] = ffma2(sp, ha[j], tp);
                ha[j].x = lky(ha[j].x); ha[j].y = lky(ha[j].y);
                hb[j] = ffma2(sp, hb[j], tp);
                hb[j].x = lky(hb[j].x); hb[j].y = lky(hb[j].y);
            }
        }
        // out = h1 @ w1^T + b1 -> BN_out -> leaky -> new x
        float2 oa[8], ob[8];
        load8s(oa, &b1q[l*4]); load8s(ob, &b1q[l*4]);
        mm16d(oa, ob, ha, hb, &w1q[l * 64]);
        {
            float2 st = bnoutq[l * 13 + n];
            float2 sp = make_float2(st.x, st.x), tp = make_float2(st.y, st.y);
#pragma unroll
            for (int j = 0; j < 8; j++) {
                oa[j] = ffma2(sp, oa[j], tp);
                oa[j].x = lky(oa[j].x); oa[j].y = lky(oa[j].y);
                xa[j] = oa[j];
                ob[j] = ffma2(sp, ob[j], tp);
                ob[j].x = lky(ob[j].x); ob[j].y = lky(ob[j].y);
                xb[j] = ob[j];
            }
        }
        if (l < 3) {
#pragma unroll
            for (int q = 0; q < 4; q++) {
                xwrA[n*4+q] = make_float4(xa[2*q].x, xa[2*q].y, xa[2*q+1].x, xa[2*q+1].y);
                xwrB[n*4+q] = make_float4(xb[2*q].x, xb[2*q].y, xb[2*q+1].x, xb[2*q+1].y);
            }
            __syncthreads();
        }
    }

    // ---- fc heads: mu, logvar (dual over the two batch elems) ----
    float2 mua[8], mub[8], lva[8], lvb[8];
    load8s(mua, fc1bq); load8s(mub, fc1bq);
    load8s(lva, fc2bq); load8s(lvb, fc2bq);
    mm16d(mua, mub, xa, xb, fc1q);
    mm16d(lva, lvb, xa, xb, fc2q);
    {
        size_t bgA = (size_t)blockIdx.x * NB + bl;
        size_t bgB = bgA + 16;
        float* muoA = d_out + 22151168ull + (bgA * 13 + n) * 16;
        float* lvoA = d_out + 28966912ull + (bgA * 13 + n) * 16;
        float* muoB = d_out + 22151168ull + (bgB * 13 + n) * 16;
        float* lvoB = d_out + 28966912ull + (bgB * 13 + n) * 16;
#pragma unroll
        for (int q = 0; q < 4; q++) {
            ((float4*)muoA)[q] = make_float4(mua[2*q].x, mua[2*q].y, mua[2*q+1].x, mua[2*q+1].y);
            ((float4*)lvoA)[q] = make_float4(lva[2*q].x, lva[2*q].y, lva[2*q+1].x, lva[2*q+1].y);
            ((float4*)muoB)[q] = make_float4(mub[2*q].x, mub[2*q].y, mub[2*q+1].x, mub[2*q+1].y);
            ((float4*)lvoB)[q] = make_float4(lvb[2*q].x, lvb[2*q].y, lvb[2*q+1].x, lvb[2*q+1].y);
        }
    }

    // Fence: layer-3 adj + x-row reads complete before tS overlay
    __syncthreads();

    // ---- decoder: temp[k][n][d] = mu @ dec_w[k]^T + dec_b[k] ----
    float4* tSA = (float4*)arA;   // [k*52 + m*4 + q], overlays adj/xb0
    float4* tSB = (float4*)arB;
#pragma unroll
    for (int k = 0; k < 4; k++) {
        float2 aa[8], ab[8];
        load8s(aa, &decbq[k*4]); load8s(ab, &decbq[k*4]);
        mm16d(aa, ab, mua, mub, &decq[k * 64]);
#pragma unroll
        for (int q = 0; q < 4; q++) {
            tSA[k*52 + n*4 + q] = make_float4(aa[2*q].x, aa[2*q].y, aa[2*q+1].x, aa[2*q+1].y);
            tSB[k*52 + n*4 + q] = make_float4(ab[2*q].x, ab[2*q].y, ab[2*q+1].x, ab[2*q+1].y);
        }
    }
    __syncthreads();

    // ---- recon: symmetric gram, compute m<=n, mirror ----
#pragma unroll
    for (int e = 0; e < 2; e++) {
        const float4* tS = e ? tSB : tSA;
        float* reconS = (float*)((e ? arB : arA) + 3328);  // [k*169 + n*13 + m]
#pragma unroll
        for (int k = 0; k < 4; k++) {
            float2 tn[8];
            {
                float4 q0 = tS[k*52+n*4+0], q1 = tS[k*52+n*4+1], q2 = tS[k*52+n*4+2], q3 = tS[k*52+n*4+3];
                tn[0] = lo2(q0); tn[1] = hi2(q0); tn[2] = lo2(q1); tn[3] = hi2(q1);
                tn[4] = lo2(q2); tn[5] = hi2(q2); tn[6] = lo2(q3); tn[7] = hi2(q3);
            }
            for (int m = 0; m <= n; m++) {
                float4 q0 = tS[k*52+m*4+0], q1 = tS[k*52+m*4+1], q2 = tS[k*52+m*4+2], q3 = tS[k*52+m*4+3];
                float2 acc = make_float2(0.f, 0.f);
                acc = ffma2(tn[0], lo2(q0), acc);  acc = ffma2(tn[1], hi2(q0), acc);
                acc = ffma2(tn[2], lo2(q1), acc);  acc = ffma2(tn[3], hi2(q1), acc);
                acc = ffma2(tn[4], lo2(q2), acc);  acc = ffma2(tn[5], hi2(q2), acc);
                acc = ffma2(tn[6], lo2(q3), acc);  acc = ffma2(tn[7], hi2(q3), acc);
                float v = fmaxf(acc.x + acc.y, 0.0f);
                reconS[k * 169 + n * 13 + m] = v;
                if (m < n) reconS[k * 169 + m * 13 + n] = v;
            }
        }
    }
    __syncthreads();

    // ---- coalesced recon flush (float4) ----
    {
        float4* outg = (float4*)d_out;
        size_t base4 = (size_t)blockIdx.x * NB * 169;
        for (int i = t; i < NB * 169; i += TPB) {       // 26 iters exactly
            int b = i / 169, q = i - b * 169;
            outg[base4 + i] = *(const float4*)(arenas + b * ARENA_BYTES + 3328 + q * 16);
        }
    }
}

extern "C" void kernel_launch(void* const* d_in, const int* in_sizes, int n_in,
                              void* d_out, int out_size) {
    (void)in_sizes; (void)n_in; (void)out_size;
    cudaFuncSetAttribute(vae_kernel, cudaFuncAttributeMaxDynamicSharedMemorySize, SMEM_TOTAL);
    vae_kernel<<<NGRID, TPB, SMEM_TOTAL>>>(
        (const float*)d_in[0],  (const float*)d_in[1],  (const float*)d_in[2],
        (const float*)d_in[3],  (const float*)d_in[4],  (const float*)d_in[5],
        (const float*)d_in[6],  (const float*)d_in[7],  (const float*)d_in[8],
        (const float*)d_in[9],  (const float*)d_in[10], (const float*)d_in[11],
        (const float*)d_in[12], (const float*)d_in[13], (const float*)d_in[14],
        (const float*)d_in[15], (const float*)d_in[16], (const float*)d_in[17],
        (const float*)d_in[18], (const float*)d_in[19], (const float*)d_in[20],
        (float*)d_out);
}